// round 7
// baseline (speedup 1.0000x reference)
#include <cuda_runtime.h>
#include <math.h>

#define H 1024
#define F 128
#define F4 32
#define MAXS 8192
#define G 592            // 148 SMs x 4 blocks — all-resident by construction
#define ABLK 32          // blocks doing phase A
#define CBLK 128         // blocks doing the qpart stage
#define BCNT (G - ABLK)  // blocks doing query colsum
#define CH 8             // E rows per dynamic grab (one per warp)
#define NCHMAX 8         // column chunks (S/1024)

// Scratch (rewritten every call; counters reset by last block => deterministic).
__device__ float g_partial[G * H];
__device__ float g_qp[CBLK * F];
__device__ float g_w[2];
__device__ float g_v0[H];
__device__ float g_v1[H];
__device__ float g_r0[MAXS];
__device__ float g_r1[MAXS];
__device__ int   g_flagA;
__device__ int   g_flagB;
__device__ int   g_flagC;
__device__ int   g_flagW;
__device__ int   g_rowctr;
__device__ int   g_cdone[NCHMAX];
__device__ int   g_tilectr;
__device__ int   g_fin;

// ---------------------------------------------------------------------------
__device__ __forceinline__ void compute_mem(float* mem,
                                            const float* ts, const float* dg,
                                            const float* Wt1, const float* bt1,
                                            const float* Wt2, const float* bt2,
                                            int t) {
    int k = t >> 7, h = t & 127;
    float tk = ts[k];
    float acc = bt2[h];
    #pragma unroll
    for (int j = 0; j < F4; ++j) {
        float a = fmaxf(fmaf(tk, Wt1[j], bt1[j]), 0.f);
        acc = fmaf(a, Wt2[j * F + h], acc);
    }
    mem[t] = dg[k * F + h] + acc;
}

// ---------------------------------------------------------------------------
// C-stage: block b (<CBLK) reduces its 8-h qmean slice + qpart partial;
// last ticket block finishes scores -> g_w, sets g_flagW.
// ---------------------------------------------------------------------------
__device__ void do_stage_C(int b, int t, float* s0, float* mem, float* qm,
                           float* qpart, int* slast,
                           const float* ts,  const float* dg,
                           const float* Wt1, const float* bt1,
                           const float* Wt2, const float* bt2,
                           const float* Wa1, const float* ba1,
                           const float* Wa2, const float* ba2, int S) {
    __threadfence();
    int h0 = b * 8;
    {
        int hl = t & 7, pl = t >> 3;
        float s = 0.f;
        for (int p = ABLK + pl; p < G; p += 32)
            s += g_partial[p * H + h0 + hl];
        s0[t] = s;
        __syncthreads();
        #pragma unroll
        for (int off = 128; off >= 8; off >>= 1) {
            if (t < off) s0[t] += s0[t + off];
            __syncthreads();
        }
        if (t < 8) qm[t] = s0[t] / (float)S;
        __syncthreads();
    }
    {
        int j = t & 127, half = t >> 7;
        float acc = 0.f;
        #pragma unroll
        for (int hl = half * 4; hl < half * 4 + 4; ++hl)
            acc = fmaf(qm[hl], Wa1[(size_t)(F + h0 + hl) * F + j], acc);
        s0[t] = acc;
        __syncthreads();
        if (t < 128) g_qp[b * F + t] = s0[t] + s0[t + 128];
    }
    __threadfence();
    __syncthreads();
    if (t == 0) *slast = (atomicAdd(&g_flagC, 1) == CBLK - 1);
    __syncthreads();
    if (!*slast) return;

    __threadfence();
    {
        int j = t & 127, half = t >> 7;
        float s = 0.f;
        for (int bb = half * (CBLK / 2); bb < (half + 1) * (CBLK / 2); ++bb)
            s += __ldcg(&g_qp[bb * F + j]);
        s0[t] = s;
    }
    compute_mem(mem, ts, dg, Wt1, bt1, Wt2, bt2, t);
    __syncthreads();
    if (t < F) qpart[t] = s0[t] + s0[t + F];
    __syncthreads();
    {
        int k = t >> 7, j = t & 127;
        float acc = ba1[j] + qpart[j];
        #pragma unroll 8
        for (int f = 0; f < F; ++f)
            acc = fmaf(mem[k * F + f], Wa1[(size_t)f * F + j], acc);
        s0[t] = tanhf(acc) * Wa2[j];
    }
    __syncthreads();
    for (int off = 64; off; off >>= 1) {
        if ((t & 127) < off) s0[t] += s0[t + off];
        __syncthreads();
    }
    if ((t & 127) == 0)
        g_w[t >> 7] = 0.5f / (1.f + expf(-(s0[t] + ba2[0])));
    __threadfence();
    __syncthreads();
    if (t == 0) atomicExch(&g_flagW, 1);
}

// ---------------------------------------------------------------------------
// The whole problem in ONE persistent kernel.
// ---------------------------------------------------------------------------
__global__ void __launch_bounds__(256, 4)
kAll(const float4* __restrict__ q4, const float4* __restrict__ key4,
     const float* __restrict__ ts,  const float* __restrict__ dg,
     const float* __restrict__ Wt1, const float* __restrict__ bt1,
     const float* __restrict__ Wt2, const float* __restrict__ bt2,
     const float* __restrict__ Wa1, const float* __restrict__ ba1,
     const float* __restrict__ Wa2, const float* __restrict__ ba2,
     const float* __restrict__ Wg,  const float* __restrict__ bg,
     float* __restrict__ out, int S) {
    __shared__ float s0[256];
    __shared__ float s1[256];
    __shared__ float mem[2 * F];
    __shared__ float qm[8];
    __shared__ float qpart[F];
    __shared__ int slast;
    __shared__ int sh_row;
    __shared__ int sh_ready;
    __shared__ int sh_tile;

    int t = threadIdx.x, b = blockIdx.x;

    if (b < ABLK) {
        // ---- A: v0/v1 h-slices (Wg^T mem + bg); skip B ----
        compute_mem(mem, ts, dg, Wt1, bt1, Wt2, bt2, t);
        __syncthreads();
        int hcol = b * 32 + (t & 31);
        int fg = t >> 5;
        float a0 = 0.f, a1 = 0.f;
        #pragma unroll
        for (int f = fg * 16; f < fg * 16 + 16; ++f) {
            float w = Wg[(size_t)f * H + hcol];
            a0 = fmaf(mem[f], w, a0);
            a1 = fmaf(mem[F + f], w, a1);
        }
        s0[t] = a0; s1[t] = a1;
        __syncthreads();
        if (t < 128) { s0[t] += s0[t + 128]; s1[t] += s1[t + 128]; }
        __syncthreads();
        if (t < 64)  { s0[t] += s0[t + 64];  s1[t] += s1[t + 64]; }
        __syncthreads();
        if (t < 32) {
            float bb = bg[hcol];
            g_v0[hcol] = s0[t] + s0[t + 32] + bb;
            g_v1[hcol] = s1[t] + s1[t + 32] + bb;
        }
        __threadfence();
        __syncthreads();
        if (t == 0) atomicAdd(&g_flagA, 1);
        __syncthreads();
    } else {
        // ---- B: query column partial sums over blocks ABLK..G-1 ----
        int bb = b - ABLK;
        int rpb = (S + BCNT - 1) / BCNT;
        int r0 = bb * rpb;
        int r1 = min(S, r0 + rpb);
        float4 acc = make_float4(0.f, 0.f, 0.f, 0.f);
        for (int r = r0; r < r1; ++r) {
            float4 v = __ldcs(q4 + (size_t)r * (H / 4) + t);
            acc.x += v.x; acc.y += v.y; acc.z += v.z; acc.w += v.w;
        }
        ((float4*)g_partial)[b * (H / 4) + t] = acc;
        __threadfence();
        __syncthreads();
        if (t == 0) atomicAdd(&g_flagB, 1);
        __syncthreads();
    }

    // ---- wait for v0/v1 ----
    if (t == 0) {
        while (*(volatile int*)&g_flagA < ABLK) __nanosleep(64);
    }
    __syncthreads();
    __threadfence();

    // ---- E: dynamic dual key matvec w/ per-chunk completion + C interleave ----
    bool needC = (b < CBLK);
    int lane = t & 31, wid = t >> 5;
    const float4* v04 = (const float4*)g_v0;
    const float4* v14 = (const float4*)g_v1;

    for (;;) {
        if (needC) {
            if (t == 0) sh_ready = (*(volatile int*)&g_flagB >= BCNT);
            __syncthreads();
            if (sh_ready) {
                do_stage_C(b, t, s0, mem, qm, qpart, &slast,
                           ts, dg, Wt1, bt1, Wt2, bt2, Wa1, ba1, Wa2, ba2, S);
                needC = false;
                __syncthreads();
            }
        }
        if (t == 0) sh_row = atomicAdd(&g_rowctr, CH);
        __syncthreads();
        int row0 = sh_row;
        if (row0 >= S) break;
        int row = row0 + wid;
        if (row < S) {
            const float4* k4p = key4 + (size_t)row * (H / 4);
            float a0 = 0.f, a1 = 0.f;
            #pragma unroll
            for (int i = 0; i < (H / 4) / 32; ++i) {
                int idx = i * 32 + lane;
                float4 kv = __ldcs(k4p + idx);
                float4 x = __ldg(v04 + idx);
                float4 y = __ldg(v14 + idx);
                a0 = fmaf(kv.x, x.x, a0); a0 = fmaf(kv.y, x.y, a0);
                a0 = fmaf(kv.z, x.z, a0); a0 = fmaf(kv.w, x.w, a0);
                a1 = fmaf(kv.x, y.x, a1); a1 = fmaf(kv.y, y.y, a1);
                a1 = fmaf(kv.z, y.z, a1); a1 = fmaf(kv.w, y.w, a1);
            }
            #pragma unroll
            for (int off = 16; off; off >>= 1) {
                a0 += __shfl_xor_sync(0xFFFFFFFFu, a0, off);
                a1 += __shfl_xor_sync(0xFFFFFFFFu, a1, off);
            }
            if (lane == 0) { g_r0[row] = a0; g_r1[row] = a1; }
        }
        __syncthreads();
        if (t == 0) {
            __threadfence();
            int nrows = min(CH, S - row0);
            atomicAdd(&g_cdone[row0 >> 10], nrows);
        }
        __syncthreads();
    }

    // Finish C if it never became ready during the row loop.
    if (needC) {
        if (t == 0) {
            while (*(volatile int*)&g_flagB < BCNT) __nanosleep(64);
        }
        __syncthreads();
        do_stage_C(b, t, s0, mem, qm, qpart, &slast,
                   ts, dg, Wt1, bt1, Wt2, bt2, Wa1, ba1, Wa2, ba2, S);
        __syncthreads();
    }

    // ---- Store phase: dynamic 32-row x 1024-col tiles, chunk-gated ----
    if (t == 0) {
        while (*(volatile int*)&g_flagW == 0) __nanosleep(64);
    }
    __syncthreads();
    __threadfence();
    float w0 = __ldcg(&g_w[0]);
    float w1 = __ldcg(&g_w[1]);

    int nch = S >> 10;               // column chunks of 1024
    int rowTiles = S >> 5;           // 32-row tiles per chunk
    int ntiles = nch * rowTiles;
    int lastch = -1;
    float4 v;                        // combined output float4 for this thread's cols

    for (;;) {
        if (t == 0) sh_tile = atomicAdd(&g_tilectr, 1);
        __syncthreads();
        int tile = sh_tile;
        if (tile >= ntiles) break;
        int ch = tile / rowTiles;
        int sub = tile - ch * rowTiles;
        if (ch != lastch) {
            int need = min(1024, S - (ch << 10));
            if (t == 0) {
                while (*(volatile int*)&g_cdone[ch] < need) __nanosleep(64);
            }
            __syncthreads();
            __threadfence();
            int c = (ch << 10) + t * 4;
            float4 a = __ldcg((const float4*)&g_r0[c]);
            float4 bb = __ldcg((const float4*)&g_r1[c]);
            v.x = fmaf(w0, a.x, w1 * bb.x);
            v.y = fmaf(w0, a.y, w1 * bb.y);
            v.z = fmaf(w0, a.z, w1 * bb.z);
            v.w = fmaf(w0, a.w, w1 * bb.w);
            lastch = ch;
        }
        float* base = out + (size_t)(sub << 5) * S + (ch << 10);
        #pragma unroll 8
        for (int r = 0; r < 32; ++r)
            __stcs((float4*)(base + (size_t)r * S) + t, v);
        __syncthreads();
    }

    // ---- last block resets all counters for graph replay ----
    if (t == 0) {
        if (atomicAdd(&g_fin, 1) == G - 1) {
            __threadfence();
            g_flagA = 0; g_flagB = 0; g_flagC = 0; g_flagW = 0;
            g_rowctr = 0; g_tilectr = 0;
            #pragma unroll
            for (int i = 0; i < NCHMAX; ++i) g_cdone[i] = 0;
            g_fin = 0;
        }
    }
}

// ---------------------------------------------------------------------------
extern "C" void kernel_launch(void* const* d_in, const int* in_sizes, int n_in,
                              void* d_out, int out_size) {
    const float* query = (const float*)d_in[0];
    const float* key   = (const float*)d_in[1];
    const float* dg    = (const float*)d_in[2];
    const float* ts    = (const float*)d_in[3];
    const float* Wt1   = (const float*)d_in[4];
    const float* bt1   = (const float*)d_in[5];
    const float* Wt2   = (const float*)d_in[6];
    const float* bt2   = (const float*)d_in[7];
    const float* Wa1   = (const float*)d_in[8];
    const float* ba1   = (const float*)d_in[9];
    const float* Wa2   = (const float*)d_in[10];
    const float* ba2   = (const float*)d_in[11];
    const float* Wg    = (const float*)d_in[12];
    const float* bg    = (const float*)d_in[13];

    int S = in_sizes[1] / H;

    kAll<<<G, 256>>>((const float4*)query, (const float4*)key,
                     ts, dg, Wt1, bt1, Wt2, bt2,
                     Wa1, ba1, Wa2, ba2, Wg, bg,
                     (float*)d_out, S);
}

// round 9
// speedup vs baseline: 1.0905x; 1.0905x over previous
#include <cuda_runtime.h>
#include <math.h>

#define H 1024
#define F 128
#define F4 32
#define MAXS 8192
#define G 592            // 148 SMs x 4 blocks — all-resident by construction
#define ABLK 32          // blocks doing phase A
#define CBLK 128         // blocks doing the qpart stage (b in [ABLK, ABLK+CBLK))
#define BCNT (G - ABLK)  // blocks doing query colsum
#define RW 4             // E rows per warp grab

// Scratch (rewritten every call; counters reset by k4 => deterministic).
__device__ float g_partial[G * H];
__device__ float g_qp[CBLK * F];
__device__ float g_w[2];
__device__ float g_v0[H];
__device__ float g_v1[H];
__device__ float g_r0[MAXS];
__device__ float g_r1[MAXS];
__device__ int   g_flagA;
__device__ int   g_flagB;
__device__ int   g_flagC;
__device__ int   g_rowctr;

// ---------------------------------------------------------------------------
__device__ __forceinline__ void compute_mem(float* mem,
                                            const float* ts, const float* dg,
                                            const float* Wt1, const float* bt1,
                                            const float* Wt2, const float* bt2,
                                            int t) {
    int k = t >> 7, h = t & 127;
    float tk = ts[k];
    float acc = bt2[h];
    #pragma unroll
    for (int j = 0; j < F4; ++j) {
        float a = fmaxf(fmaf(tk, Wt1[j], bt1[j]), 0.f);
        acc = fmaf(a, Wt2[j * F + h], acc);
    }
    mem[t] = dg[k * F + h] + acc;
}

// ---------------------------------------------------------------------------
// C-stage: C-block cb (0..CBLK-1) reduces its 8-h qmean slice + qpart partial;
// last ticket block finishes scores -> g_w.
// ---------------------------------------------------------------------------
__device__ void do_stage_C(int cb, int t, float* s0, float* mem, float* qm,
                           float* qpart, int* slast,
                           const float* ts,  const float* dg,
                           const float* Wt1, const float* bt1,
                           const float* Wt2, const float* bt2,
                           const float* Wa1, const float* ba1,
                           const float* Wa2, const float* ba2, int S) {
    __threadfence();
    int h0 = cb * 8;
    {
        int hl = t & 7, pl = t >> 3;
        float s = 0.f;
        for (int p = ABLK + pl; p < G; p += 32)   // only blocks >= ABLK wrote partials
            s += g_partial[p * H + h0 + hl];
        s0[t] = s;
        __syncthreads();
        #pragma unroll
        for (int off = 128; off >= 8; off >>= 1) {
            if (t < off) s0[t] += s0[t + off];
            __syncthreads();
        }
        if (t < 8) qm[t] = s0[t] / (float)S;
        __syncthreads();
    }
    {
        int j = t & 127, half = t >> 7;
        float acc = 0.f;
        #pragma unroll
        for (int hl = half * 4; hl < half * 4 + 4; ++hl)
            acc = fmaf(qm[hl], Wa1[(size_t)(F + h0 + hl) * F + j], acc);
        s0[t] = acc;
        __syncthreads();
        if (t < 128) g_qp[cb * F + t] = s0[t] + s0[t + 128];
    }
    __threadfence();
    __syncthreads();
    if (t == 0) *slast = (atomicAdd(&g_flagC, 1) == CBLK - 1);
    __syncthreads();
    if (!*slast) return;

    __threadfence();
    {
        int j = t & 127, half = t >> 7;
        float s = 0.f;
        for (int bb = half * (CBLK / 2); bb < (half + 1) * (CBLK / 2); ++bb)
            s += __ldcg(&g_qp[bb * F + j]);
        s0[t] = s;
    }
    compute_mem(mem, ts, dg, Wt1, bt1, Wt2, bt2, t);
    __syncthreads();
    if (t < F) qpart[t] = s0[t] + s0[t + F];
    __syncthreads();
    {
        int k = t >> 7, j = t & 127;
        float acc = ba1[j] + qpart[j];
        #pragma unroll 8
        for (int f = 0; f < F; ++f)
            acc = fmaf(mem[k * F + f], Wa1[(size_t)f * F + j], acc);
        s0[t] = tanhf(acc) * Wa2[j];
    }
    __syncthreads();
    for (int off = 64; off; off >>= 1) {
        if ((t & 127) < off) s0[t] += s0[t + off];
        __syncthreads();
    }
    if ((t & 127) == 0)
        g_w[t >> 7] = 0.5f / (1.f + expf(-(s0[t] + ba2[0])));
}

// ---------------------------------------------------------------------------
__global__ void __launch_bounds__(256, 4)
kPre(const float4* __restrict__ q4, const float4* __restrict__ key4,
     const float* __restrict__ ts,  const float* __restrict__ dg,
     const float* __restrict__ Wt1, const float* __restrict__ bt1,
     const float* __restrict__ Wt2, const float* __restrict__ bt2,
     const float* __restrict__ Wa1, const float* __restrict__ ba1,
     const float* __restrict__ Wa2, const float* __restrict__ ba2,
     const float* __restrict__ Wg,  const float* __restrict__ bg,
     int S) {
    __shared__ float s0[256];
    __shared__ float s1[256];
    __shared__ float mem[2 * F];
    __shared__ float qm[8];
    __shared__ float qpart[F];
    __shared__ int slast;

    int t = threadIdx.x, b = blockIdx.x;

    if (b < ABLK) {
        // ---- A: v0/v1 h-slices (Wg^T mem + bg) ----
        compute_mem(mem, ts, dg, Wt1, bt1, Wt2, bt2, t);
        __syncthreads();
        int hcol = b * 32 + (t & 31);
        int fg = t >> 5;
        float a0 = 0.f, a1 = 0.f;
        #pragma unroll
        for (int f = fg * 16; f < fg * 16 + 16; ++f) {
            float w = Wg[(size_t)f * H + hcol];
            a0 = fmaf(mem[f], w, a0);
            a1 = fmaf(mem[F + f], w, a1);
        }
        s0[t] = a0; s1[t] = a1;
        __syncthreads();
        if (t < 128) { s0[t] += s0[t + 128]; s1[t] += s1[t + 128]; }
        __syncthreads();
        if (t < 64)  { s0[t] += s0[t + 64];  s1[t] += s1[t + 64]; }
        __syncthreads();
        if (t < 32) {
            float bb = bg[hcol];
            g_v0[hcol] = s0[t] + s0[t + 32] + bb;
            g_v1[hcol] = s1[t] + s1[t + 32] + bb;
        }
        __threadfence();
        __syncthreads();
        if (t == 0) atomicAdd(&g_flagA, 1);
        __syncthreads();
    } else {
        // ---- B: query column partial sums over blocks ABLK..G-1 ----
        int bb = b - ABLK;
        int rpb = (S + BCNT - 1) / BCNT;
        int r0 = bb * rpb;
        int r1 = min(S, r0 + rpb);
        float4 acc = make_float4(0.f, 0.f, 0.f, 0.f);
        for (int r = r0; r < r1; ++r) {
            float4 v = __ldcs(q4 + (size_t)r * (H / 4) + t);
            acc.x += v.x; acc.y += v.y; acc.z += v.z; acc.w += v.w;
        }
        ((float4*)g_partial)[b * (H / 4) + t] = acc;
        __threadfence();
        __syncthreads();
        if (t == 0) atomicAdd(&g_flagB, 1);
        __syncthreads();

        // ---- C: blocks [ABLK, ABLK+CBLK) own the qpart h-slices ----
        if (bb < CBLK) {
            if (t == 0) {
                while (*(volatile int*)&g_flagB < BCNT) __nanosleep(64);
            }
            __syncthreads();
            do_stage_C(bb, t, s0, mem, qm, qpart, &slast,
                       ts, dg, Wt1, bt1, Wt2, bt2, Wa1, ba1, Wa2, ba2, S);
            __syncthreads();
        }
    }

    // ---- wait for v0/v1 ----
    if (t == 0) {
        while (*(volatile int*)&g_flagA < ABLK) __nanosleep(64);
    }
    __syncthreads();
    __threadfence();

    // ---- E: warp-autonomous dual key matvec (no block syncs) ----
    int lane = t & 31;
    const float4* v04 = (const float4*)g_v0;
    const float4* v14 = (const float4*)g_v1;

    for (;;) {
        int row0 = 0;
        if (lane == 0) row0 = atomicAdd(&g_rowctr, RW);
        row0 = __shfl_sync(0xFFFFFFFFu, row0, 0);
        if (row0 >= S) break;
        #pragma unroll
        for (int rr = 0; rr < RW; ++rr) {
            int row = row0 + rr;
            if (row >= S) break;
            const float4* k4p = key4 + (size_t)row * (H / 4);
            float a0 = 0.f, a1 = 0.f;
            #pragma unroll
            for (int i = 0; i < (H / 4) / 32; ++i) {
                int idx = i * 32 + lane;
                float4 kv = __ldcs(k4p + idx);
                float4 x = __ldg(v04 + idx);
                float4 y = __ldg(v14 + idx);
                a0 = fmaf(kv.x, x.x, a0); a0 = fmaf(kv.y, x.y, a0);
                a0 = fmaf(kv.z, x.z, a0); a0 = fmaf(kv.w, x.w, a0);
                a1 = fmaf(kv.x, y.x, a1); a1 = fmaf(kv.y, y.y, a1);
                a1 = fmaf(kv.z, y.z, a1); a1 = fmaf(kv.w, y.w, a1);
            }
            #pragma unroll
            for (int off = 16; off; off >>= 1) {
                a0 += __shfl_xor_sync(0xFFFFFFFFu, a0, off);
                a1 += __shfl_xor_sync(0xFFFFFFFFu, a1, off);
            }
            if (lane == 0) { g_r0[row] = a0; g_r1[row] = a1; }
        }
    }
}

// ---------------------------------------------------------------------------
// K4: out[row][s] = w0*r0[s] + w1*r1[s]; resets counters for graph replay.
// ---------------------------------------------------------------------------
__global__ void k4_bcast(float* __restrict__ out, int S) {
    if (blockIdx.x == 0 && threadIdx.x == 0) {
        g_flagA = 0; g_flagB = 0; g_flagC = 0; g_rowctr = 0;
    }
    __shared__ float wsh[2];
    if (threadIdx.x < 2) wsh[threadIdx.x] = g_w[threadIdx.x];
    __syncthreads();
    float w0 = wsh[0], w1 = wsh[1];
    int row = blockIdx.x;
    const float4* r04 = (const float4*)g_r0;
    const float4* r14 = (const float4*)g_r1;
    float4* o4 = (float4*)(out + (size_t)row * S);
    int n4 = S >> 2;
    for (int c = threadIdx.x; c < n4; c += blockDim.x) {
        float4 a = __ldg(r04 + c);
        float4 b = __ldg(r14 + c);
        float4 v;
        v.x = fmaf(w0, a.x, w1 * b.x);
        v.y = fmaf(w0, a.y, w1 * b.y);
        v.z = fmaf(w0, a.z, w1 * b.z);
        v.w = fmaf(w0, a.w, w1 * b.w);
        __stcs(o4 + c, v);
    }
}

// ---------------------------------------------------------------------------
extern "C" void kernel_launch(void* const* d_in, const int* in_sizes, int n_in,
                              void* d_out, int out_size) {
    const float* query = (const float*)d_in[0];
    const float* key   = (const float*)d_in[1];
    const float* dg    = (const float*)d_in[2];
    const float* ts    = (const float*)d_in[3];
    const float* Wt1   = (const float*)d_in[4];
    const float* bt1   = (const float*)d_in[5];
    const float* Wt2   = (const float*)d_in[6];
    const float* bt2   = (const float*)d_in[7];
    const float* Wa1   = (const float*)d_in[8];
    const float* ba1   = (const float*)d_in[9];
    const float* Wa2   = (const float*)d_in[10];
    const float* ba2   = (const float*)d_in[11];
    const float* Wg    = (const float*)d_in[12];
    const float* bg    = (const float*)d_in[13];

    int S = in_sizes[1] / H;

    kPre<<<G, 256>>>((const float4*)query, (const float4*)key,
                     ts, dg, Wt1, bt1, Wt2, bt2,
                     Wa1, ba1, Wa2, ba2, Wg, bg, S);
    k4_bcast<<<S, 256>>>((float*)d_out, S);
}